// round 5
// baseline (speedup 1.0000x reference)
#include <cuda_runtime.h>
#include <math.h>
#include <stdint.h>

// Problem constants
#define Bq   4
#define Tq   2048
#define Eq   1024
#define Hq   16
#define Dq   64
#define BHq  (Bq*Hq)

typedef unsigned long long ull;

// Scratch (alloc-free rule: static __device__ arrays). 32 MB each.
__device__ float g_Q [(size_t)BHq * Tq * Dq];   // pre-scaled by 0.125*log2(e)
__device__ float g_K [(size_t)BHq * Tq * Dq];   // d-columns pair-permuted
__device__ float g_V [(size_t)BHq * Tq * Dq];   // row-major (residual/epilogue)
__device__ float g_Vt[(size_t)BHq * Dq * Tq];   // transposed, t pair-permuted

#define SCALE_LOG2E 0.18033688011112042f   // 0.125 * log2(e)

// ---- packed f32x2 helpers (proj kernel) ----
__device__ __forceinline__ ull ffma2(ull a, ull b, ull c) {
    ull d; asm("fma.rn.f32x2 %0, %1, %2, %3;" : "=l"(d) : "l"(a), "l"(b), "l"(c)); return d;
}
__device__ __forceinline__ float2 unpack2(ull v) {
    float lo, hi; asm("mov.b64 {%0, %1}, %2;" : "=f"(lo), "=f"(hi) : "l"(v));
    return make_float2(lo, hi);
}

// ---- warp-level tf32 MMA: D(16x8) += A(16x8) * B(8x8) ----
__device__ __forceinline__ void mma_tf32(float c[4], const uint32_t a[4], const uint32_t b[2]) {
    asm volatile(
        "mma.sync.aligned.m16n8k8.row.col.f32.tf32.tf32.f32 "
        "{%0,%1,%2,%3}, {%4,%5,%6,%7}, {%8,%9}, {%0,%1,%2,%3};"
        : "+f"(c[0]), "+f"(c[1]), "+f"(c[2]), "+f"(c[3])
        : "r"(a[0]), "r"(a[1]), "r"(a[2]), "r"(a[3]), "r"(b[0]), "r"(b[1]));
}

__device__ __forceinline__ float ex2f(float x) {
    float r; asm("ex2.approx.f32 %0, %1;" : "=f"(r) : "f"(x)); return r;
}
__device__ __forceinline__ uint32_t f2u(float x) { return __float_as_uint(x); }
__device__ __forceinline__ uint32_t smem_u32(const void* p) {
    uint32_t a;
    asm("{ .reg .u64 t; cvta.to.shared.u64 t, %1; cvt.u32.u64 %0, t; }" : "=r"(a) : "l"(p));
    return a;
}

#define CP_ASYNC16(dst_u32, src_ptr) \
    asm volatile("cp.async.ca.shared.global [%0], [%1], 16;" :: "r"(dst_u32), "l"(src_ptr) : "memory")
#define CP_COMMIT() asm volatile("cp.async.commit_group;" ::: "memory")
#define CP_WAIT(n)  asm volatile("cp.async.wait_group %0;" :: "n"(n) : "memory")

// pair-permutation within each 8-block: puts (i, i+4) at adjacent (2i, 2i+1).
__device__ __forceinline__ int perm8(int c) {
    return (c & ~7) | (((c & 3) << 1) | ((c >> 2) & 1));
}

// ============================================================================
// Kernel 1: shared per-head projections.
//   Q: scaled by SCALE_LOG2E, row-major.
//   K: d-columns pair-permuted, row-major.
//   V: row-major (residual) AND transposed+t-permuted into g_Vt.
// ============================================================================
__global__ void __launch_bounds__(64) proj_kernel(
    const float* __restrict__ x,
    const float* __restrict__ Wq,
    const float* __restrict__ Wk,
    const float* __restrict__ Wv)
{
    __shared__ __align__(16) float sW[64 * 64];
    __shared__ __align__(16) float sx[64 * 68];

    const int tid = threadIdx.x;
    const int bh  = blockIdx.y;
    const int b   = bh >> 4;
    const int h   = bh & 15;
    const int t0  = blockIdx.x * 64;
    const int t   = t0 + tid;

    const float* xb = x + ((size_t)(b * Tq + t0)) * Eq + h * Dq;
    for (int r = 0; r < 64; ++r)
        sx[r * 68 + tid] = xb[(size_t)r * Eq + tid];

    ull xr[32];
    bool xr_loaded = false;

    #pragma unroll 1
    for (int m = 0; m < 3; ++m) {
        __syncthreads();
        const float* Wsel = (m == 0) ? Wq : ((m == 1) ? Wk : Wv);
        {
            const float4* src = (const float4*)Wsel;
            float4* dst = (float4*)sW;
            #pragma unroll
            for (int i = 0; i < 16; ++i)
                dst[tid + 64 * i] = src[tid + 64 * i];
        }
        __syncthreads();

        if (!xr_loaded) {
            const ulonglong2* row = (const ulonglong2*)(sx + tid * 68);
            #pragma unroll
            for (int i = 0; i < 16; ++i) {
                ulonglong2 v = row[i];
                xr[2 * i] = v.x; xr[2 * i + 1] = v.y;
            }
            xr_loaded = true;
        }

        float* gq  = g_Q + ((size_t)bh * Tq + t) * Dq;
        float* gk  = g_K + ((size_t)bh * Tq + t) * Dq;
        float* gv  = g_V + ((size_t)bh * Tq + t) * Dq;
        float* gvt = g_Vt + (size_t)bh * Dq * Tq + perm8(t0 + tid);

        #pragma unroll 1
        for (int q0 = 0; q0 < 64; q0 += 4) {
            float acc[4];
            #pragma unroll
            for (int qi = 0; qi < 4; ++qi) {
                const ulonglong2* wr = (const ulonglong2*)(sW + (q0 + qi) * 64);
                ull a0 = 0ull, a1 = 0ull;
                #pragma unroll
                for (int i = 0; i < 16; ++i) {
                    ulonglong2 w = wr[i];
                    a0 = ffma2(xr[2 * i],     w.x, a0);
                    a1 = ffma2(xr[2 * i + 1], w.y, a1);
                }
                float2 f0 = unpack2(a0), f1 = unpack2(a1);
                acc[qi] = (f0.x + f0.y) + (f1.x + f1.y);
            }
            if (m == 0) {
                *(float4*)(gq + q0) = make_float4(acc[0] * SCALE_LOG2E, acc[1] * SCALE_LOG2E,
                                                  acc[2] * SCALE_LOG2E, acc[3] * SCALE_LOG2E);
            } else if (m == 1) {
                #pragma unroll
                for (int qi = 0; qi < 4; ++qi)
                    gk[perm8(q0 + qi)] = acc[qi];
            } else {
                *(float4*)(gv + q0) = make_float4(acc[0], acc[1], acc[2], acc[3]);
                #pragma unroll
                for (int qi = 0; qi < 4; ++qi)
                    gvt[(size_t)(q0 + qi) * Tq] = acc[qi];
            }
        }
    }
}

// ============================================================================
// Kernel 2: mma.sync tf32 flash attention — occupancy edition.
//   CTA = 64 queries; 4 warps x 16 rows; 128 regs cap => 4 CTAs/SM (16 warps).
//   Single-buffered K/Vt tiles (64 keys), staged via cp.async.
// ============================================================================
#define QBLK 64
#define KBLK 64
#define PKV  72                       // sK / sVt pitch: .64 frags conflict-free
#define PP   68                       // sP pitch: .32 A-frags conflict-free
#define FBUF (64 * PKV)               // 4608 floats per matrix tile
#define OFFP (2 * FBUF)               // 9216 floats (K + Vt)
#define SMF_TOTAL (OFFP + 4 * 16 * PP)   // 13568 floats = 54272 B

__global__ void __launch_bounds__(128, 4) attn_kernel(float* __restrict__ out)
{
    extern __shared__ __align__(16) float sm[];

    const int tid  = threadIdx.x;
    const int lane = tid & 31;
    const int wid  = tid >> 5;
    const int lg   = lane >> 2;
    const int lt   = lane & 3;
    float* sP = sm + OFFP + wid * 16 * PP;

    const int bh = blockIdx.y;
    const int b  = bh >> 4;
    const int h  = bh & 15;
    const int q0 = blockIdx.x * QBLK;
    const int wq = q0 + wid * 16;

    const uint32_t smb = smem_u32(sm);
    const float* gKb  = g_K  + (size_t)bh * Tq * Dq;
    const float* gVtb = g_Vt + (size_t)bh * Dq * Tq;

    // ---- Q fragments (pre-scaled in proj): A m16k8 x 8 = 32 regs ----
    uint32_t aQ[8][4];
    {
        const float* Qb = g_Q + ((size_t)bh * Tq + wq) * Dq;
        #pragma unroll
        for (int k = 0; k < 8; ++k) {
            const int c0 = k * 8 + lt;
            aQ[k][0] = f2u(Qb[(size_t)lg * Dq + c0]);
            aQ[k][1] = f2u(Qb[(size_t)(lg + 8) * Dq + c0]);
            aQ[k][2] = f2u(Qb[(size_t)lg * Dq + c0 + 4]);
            aQ[k][3] = f2u(Qb[(size_t)(lg + 8) * Dq + c0 + 4]);
        }
    }

    float o[8][4];
    #pragma unroll
    for (int nt = 0; nt < 8; ++nt)
        #pragma unroll
        for (int e = 0; e < 4; ++e) o[nt][e] = 0.f;

    float rs0 = 0.f, rs1 = 0.f;   // row sums: rows wq+lg, wq+lg+8

    #pragma unroll 1
    for (int it = 0; it < Tq / KBLK; ++it) {
        __syncthreads();   // all warps done with previous tile

        // ---- stage K,Vt tiles (cp.async, single buffer) ----
        {
            const float* gk = gKb + (size_t)it * KBLK * Dq;
            const int s0 = it * KBLK;
            #pragma unroll
            for (int j = 0; j < 8; ++j) {
                const int f = tid + 128 * j;
                const int r = f >> 4, c4 = f & 15;
                CP_ASYNC16(smb + (uint32_t)(r * PKV + 4 * c4) * 4u, gk + (size_t)f * 4);
                CP_ASYNC16(smb + (uint32_t)(FBUF + r * PKV + 4 * c4) * 4u,
                           gVtb + (size_t)r * Tq + s0 + 4 * c4);
            }
        }
        CP_COMMIT();
        CP_WAIT(0);
        __syncthreads();

        const float* sK  = sm;
        const float* sVt = sm + FBUF;

        // ---- QK^T: S(16x64) = Q * K^T ----
        float c[8][4];
        #pragma unroll
        for (int nt = 0; nt < 8; ++nt)
            #pragma unroll
            for (int e = 0; e < 4; ++e) c[nt][e] = 0.f;

        #pragma unroll
        for (int k = 0; k < 8; ++k) {
            #pragma unroll
            for (int nt = 0; nt < 8; ++nt) {
                const int s = nt * 8 + lg;
                float2 v = *(const float2*)(sK + s * PKV + k * 8 + 2 * lt);
                uint32_t bf[2] = { f2u(v.x), f2u(v.y) };
                mma_tf32(c[nt], aQ[k], bf);
            }
        }

        // ---- exp (scale pre-folded), row sums, store P ----
        #pragma unroll
        for (int nt = 0; nt < 8; ++nt) {
            float p0 = ex2f(c[nt][0]);
            float p1 = ex2f(c[nt][1]);
            float p2 = ex2f(c[nt][2]);
            float p3 = ex2f(c[nt][3]);
            rs0 += p0 + p1;
            rs1 += p2 + p3;
            const int col = nt * 8 + 2 * lt;
            *(float2*)(sP + lg * PP + col)       = make_float2(p0, p1);
            *(float2*)(sP + (lg + 8) * PP + col) = make_float2(p2, p3);
        }
        __syncwarp();   // sP warp-private: order STS -> LDS

        // ---- PV: O(16x64) += P(16x64) * V(64x64) ----
        #pragma unroll
        for (int k = 0; k < 8; ++k) {
            uint32_t ap[4];
            const int s = k * 8 + lt;
            ap[0] = f2u(sP[lg * PP + s]);
            ap[1] = f2u(sP[(lg + 8) * PP + s]);
            ap[2] = f2u(sP[lg * PP + s + 4]);
            ap[3] = f2u(sP[(lg + 8) * PP + s + 4]);
            #pragma unroll
            for (int nt = 0; nt < 8; ++nt) {
                const int d = nt * 8 + lg;
                float2 v = *(const float2*)(sVt + d * PKV + k * 8 + 2 * lt);
                uint32_t bv[2] = { f2u(v.x), f2u(v.y) };
                mma_tf32(o[nt], ap, bv);
            }
        }
    }

    // ---- row sums (reduce over the 4 lanes of each row quad) ----
    float v0 = rs0, v1 = rs1;
    v0 += __shfl_xor_sync(0xffffffffu, v0, 1);
    v0 += __shfl_xor_sync(0xffffffffu, v0, 2);
    v1 += __shfl_xor_sync(0xffffffffu, v1, 1);
    v1 += __shfl_xor_sync(0xffffffffu, v1, 2);
    const float inv0 = 1.f / v0;
    const float inv1 = 1.f / v1;

    // ---- epilogue: O/l + V residual -> out[b, t, h*64 + d] ----
    #pragma unroll
    for (int half = 0; half < 2; ++half) {
        const int t = wq + half * 8 + lg;
        const float iv = half ? inv1 : inv0;
        const float2* vr = (const float2*)(g_V + ((size_t)bh * Tq + t) * Dq);
        float2* op = (float2*)(out + ((size_t)(b * Tq + t)) * Eq + h * Dq);
        #pragma unroll
        for (int nt = 0; nt < 8; ++nt) {
            const int idx = nt * 4 + lt;
            float2 v = vr[idx];
            op[idx] = make_float2(o[nt][half * 2 + 0] * iv + v.x,
                                  o[nt][half * 2 + 1] * iv + v.y);
        }
    }
}

// ============================================================================
extern "C" void kernel_launch(void* const* d_in, const int* in_sizes, int n_in,
                              void* d_out, int out_size)
{
    const float* x  = (const float*)d_in[0];
    const float* Wq = (const float*)d_in[1];
    const float* Wk = (const float*)d_in[2];
    const float* Wv = (const float*)d_in[3];
    float* out = (float*)d_out;

    const int smem_bytes = SMF_TOTAL * 4;   // 54272 B
    cudaFuncSetAttribute(attn_kernel, cudaFuncAttributeMaxDynamicSharedMemorySize, smem_bytes);

    dim3 pgrid(Tq / 64, BHq);
    proj_kernel<<<pgrid, 64>>>(x, Wq, Wk, Wv);

    dim3 agrid(Tq / QBLK, BHq);
    attn_kernel<<<agrid, 128, smem_bytes>>>(out);
}

// round 6
// speedup vs baseline: 1.3780x; 1.3780x over previous
#include <cuda_runtime.h>
#include <math.h>
#include <stdint.h>

// Problem constants
#define Bq   4
#define Tq   2048
#define Eq   1024
#define Hq   16
#define Dq   64
#define BHq  (Bq*Hq)

typedef unsigned long long ull;

// Scratch (alloc-free rule: static __device__ arrays). 32 MB each.
__device__ float g_Q [(size_t)BHq * Tq * Dq];   // pre-scaled by 0.125*log2(e)
__device__ float g_K [(size_t)BHq * Tq * Dq];   // d-columns pair-permuted
__device__ float g_V [(size_t)BHq * Tq * Dq];   // row-major (residual/epilogue)
__device__ float g_Vt[(size_t)BHq * Dq * Tq];   // transposed (identity order)

#define SCALE_LOG2E 0.18033688011112042f   // 0.125 * log2(e)

// ---- packed f32x2 helpers (proj kernel) ----
__device__ __forceinline__ ull ffma2(ull a, ull b, ull c) {
    ull d; asm("fma.rn.f32x2 %0, %1, %2, %3;" : "=l"(d) : "l"(a), "l"(b), "l"(c)); return d;
}
__device__ __forceinline__ float2 unpack2(ull v) {
    float lo, hi; asm("mov.b64 {%0, %1}, %2;" : "=f"(lo), "=f"(hi) : "l"(v));
    return make_float2(lo, hi);
}

__device__ __forceinline__ uint32_t f2u(float x) { return __float_as_uint(x); }

// ---- warp-level tf32 MMA: D(16x8) += A(16x8) * B(8x8) ----
__device__ __forceinline__ void mma_tf32(float c[4], const uint32_t a[4], const uint32_t b[2]) {
    asm volatile(
        "mma.sync.aligned.m16n8k8.row.col.f32.tf32.tf32.f32 "
        "{%0,%1,%2,%3}, {%4,%5,%6,%7}, {%8,%9}, {%0,%1,%2,%3};"
        : "+f"(c[0]), "+f"(c[1]), "+f"(c[2]), "+f"(c[3])
        : "r"(a[0]), "r"(a[1]), "r"(a[2]), "r"(a[3]), "r"(b[0]), "r"(b[1]));
}
// scalar-operand variant (lets us reorder C-frag -> A-frag for free)
__device__ __forceinline__ void mma_tf32s(float c[4], float a0, float a1, float a2, float a3,
                                          float b0, float b1) {
    asm volatile(
        "mma.sync.aligned.m16n8k8.row.col.f32.tf32.tf32.f32 "
        "{%0,%1,%2,%3}, {%4,%5,%6,%7}, {%8,%9}, {%0,%1,%2,%3};"
        : "+f"(c[0]), "+f"(c[1]), "+f"(c[2]), "+f"(c[3])
        : "r"(f2u(a0)), "r"(f2u(a1)), "r"(f2u(a2)), "r"(f2u(a3)),
          "r"(f2u(b0)), "r"(f2u(b1)));
}

__device__ __forceinline__ float ex2f(float x) {
    float r; asm("ex2.approx.f32 %0, %1;" : "=f"(r) : "f"(x)); return r;
}
__device__ __forceinline__ uint32_t smem_u32(const void* p) {
    uint32_t a;
    asm("{ .reg .u64 t; cvta.to.shared.u64 t, %1; cvt.u32.u64 %0, t; }" : "=r"(a) : "l"(p));
    return a;
}

#define CP_ASYNC16(dst_u32, src_ptr) \
    asm volatile("cp.async.ca.shared.global [%0], [%1], 16;" :: "r"(dst_u32), "l"(src_ptr) : "memory")
#define CP_COMMIT() asm volatile("cp.async.commit_group;" ::: "memory")
#define CP_WAIT(n)  asm volatile("cp.async.wait_group %0;" :: "n"(n) : "memory")

// pair-permutation within each 8-block: puts (i, i+4) at adjacent (2i, 2i+1).
__device__ __forceinline__ int perm8(int c) {
    return (c & ~7) | (((c & 3) << 1) | ((c >> 2) & 1));
}

// ============================================================================
// Kernel 1: shared per-head projections.
//   Q: scaled by SCALE_LOG2E, row-major.
//   K: d-columns pair-permuted, row-major.
//   V: row-major (residual) AND transposed (identity) into g_Vt.
// ============================================================================
__global__ void __launch_bounds__(64) proj_kernel(
    const float* __restrict__ x,
    const float* __restrict__ Wq,
    const float* __restrict__ Wk,
    const float* __restrict__ Wv)
{
    __shared__ __align__(16) float sW[64 * 64];
    __shared__ __align__(16) float sx[64 * 68];

    const int tid = threadIdx.x;
    const int bh  = blockIdx.y;
    const int b   = bh >> 4;
    const int h   = bh & 15;
    const int t0  = blockIdx.x * 64;
    const int t   = t0 + tid;

    const float* xb = x + ((size_t)(b * Tq + t0)) * Eq + h * Dq;
    for (int r = 0; r < 64; ++r)
        sx[r * 68 + tid] = xb[(size_t)r * Eq + tid];

    ull xr[32];
    bool xr_loaded = false;

    #pragma unroll 1
    for (int m = 0; m < 3; ++m) {
        __syncthreads();
        const float* Wsel = (m == 0) ? Wq : ((m == 1) ? Wk : Wv);
        {
            const float4* src = (const float4*)Wsel;
            float4* dst = (float4*)sW;
            #pragma unroll
            for (int i = 0; i < 16; ++i)
                dst[tid + 64 * i] = src[tid + 64 * i];
        }
        __syncthreads();

        if (!xr_loaded) {
            const ulonglong2* row = (const ulonglong2*)(sx + tid * 68);
            #pragma unroll
            for (int i = 0; i < 16; ++i) {
                ulonglong2 v = row[i];
                xr[2 * i] = v.x; xr[2 * i + 1] = v.y;
            }
            xr_loaded = true;
        }

        float* gq  = g_Q + ((size_t)bh * Tq + t) * Dq;
        float* gk  = g_K + ((size_t)bh * Tq + t) * Dq;
        float* gv  = g_V + ((size_t)bh * Tq + t) * Dq;
        float* gvt = g_Vt + (size_t)bh * Dq * Tq + t;

        #pragma unroll 1
        for (int q0 = 0; q0 < 64; q0 += 4) {
            float acc[4];
            #pragma unroll
            for (int qi = 0; qi < 4; ++qi) {
                const ulonglong2* wr = (const ulonglong2*)(sW + (q0 + qi) * 64);
                ull a0 = 0ull, a1 = 0ull;
                #pragma unroll
                for (int i = 0; i < 16; ++i) {
                    ulonglong2 w = wr[i];
                    a0 = ffma2(xr[2 * i],     w.x, a0);
                    a1 = ffma2(xr[2 * i + 1], w.y, a1);
                }
                float2 f0 = unpack2(a0), f1 = unpack2(a1);
                acc[qi] = (f0.x + f0.y) + (f1.x + f1.y);
            }
            if (m == 0) {
                *(float4*)(gq + q0) = make_float4(acc[0] * SCALE_LOG2E, acc[1] * SCALE_LOG2E,
                                                  acc[2] * SCALE_LOG2E, acc[3] * SCALE_LOG2E);
            } else if (m == 1) {
                #pragma unroll
                for (int qi = 0; qi < 4; ++qi)
                    gk[perm8(q0 + qi)] = acc[qi];
            } else {
                *(float4*)(gv + q0) = make_float4(acc[0], acc[1], acc[2], acc[3]);
                #pragma unroll
                for (int qi = 0; qi < 4; ++qi)
                    gvt[(size_t)(q0 + qi) * Tq] = acc[qi];
            }
        }
    }
}

// ============================================================================
// Kernel 2: mma.sync tf32 flash attention — P-in-registers edition.
//   CTA = 256 queries; 8 warps x 32 rows. K-tiles of 64, double-buffered
//   cp.async. Scores exp'd in registers and fed straight back as A-fragments
//   (C-layout == A-layout under the s-permutation absorbed by Vt ordering).
// ============================================================================
#define QBLK 256
#define KBLK 64
#define PKV  72                       // sK / sVt pitch: .64 frags conflict-free
#define FBUF (64 * PKV)               // 4608 floats per matrix tile
#define SMF_TOTAL (4 * FBUF)          // 18432 floats = 73728 B

__global__ void __launch_bounds__(256, 1) attn_kernel(float* __restrict__ out)
{
    extern __shared__ __align__(16) float sm[];

    const int tid  = threadIdx.x;
    const int lane = tid & 31;
    const int wid  = tid >> 5;
    const int lg   = lane >> 2;
    const int lt   = lane & 3;

    const int bh = blockIdx.y;
    const int b  = bh >> 4;
    const int h  = bh & 15;
    const int q0 = blockIdx.x * QBLK;
    const int wq = q0 + wid * 32;

    const uint32_t smb = smem_u32(sm);
    const float* gKb  = g_K  + (size_t)bh * Tq * Dq;
    const float* gVtb = g_Vt + (size_t)bh * Dq * Tq;

    // ---- Q fragments (pre-scaled in proj): 64 regs ----
    uint32_t aQ[2][8][4];
    {
        const float* Qb = g_Q + ((size_t)bh * Tq + wq) * Dq;
        #pragma unroll
        for (int mt = 0; mt < 2; ++mt) {
            const int r0 = mt * 16 + lg;
            #pragma unroll
            for (int k = 0; k < 8; ++k) {
                const int c0 = k * 8 + lt;
                aQ[mt][k][0] = f2u(Qb[(size_t)r0 * Dq + c0]);
                aQ[mt][k][1] = f2u(Qb[(size_t)(r0 + 8) * Dq + c0]);
                aQ[mt][k][2] = f2u(Qb[(size_t)r0 * Dq + c0 + 4]);
                aQ[mt][k][3] = f2u(Qb[(size_t)(r0 + 8) * Dq + c0 + 4]);
            }
        }
    }

    float o[2][8][4];
    #pragma unroll
    for (int mt = 0; mt < 2; ++mt)
        #pragma unroll
        for (int nt = 0; nt < 8; ++nt)
            #pragma unroll
            for (int e = 0; e < 4; ++e) o[mt][nt][e] = 0.f;

    float rs[4] = {0.f, 0.f, 0.f, 0.f};

    // ---- staging helper (cp.async, 8 x 16B per thread) ----
    auto stage = [&](int it, int buf) {
        const uint32_t sKu  = smb + (uint32_t)(buf * 2 * FBUF) * 4u;
        const uint32_t sVtu = sKu + (uint32_t)FBUF * 4u;
        const float* gk = gKb + (size_t)it * KBLK * Dq;
        const int s0 = it * KBLK;
        #pragma unroll
        for (int j = 0; j < 4; ++j) {
            const int f = tid + 256 * j;
            const int r = f >> 4, c4 = f & 15;
            CP_ASYNC16(sKu + (uint32_t)(r * PKV + 4 * c4) * 4u, gk + (size_t)f * 4);
            CP_ASYNC16(sVtu + (uint32_t)(r * PKV + 4 * c4) * 4u,
                       gVtb + (size_t)r * Tq + s0 + 4 * c4);
        }
    };

    stage(0, 0);
    CP_COMMIT();

    #pragma unroll 1
    for (int it = 0; it < Tq / KBLK; ++it) {
        const int cur = it & 1;
        if (it < Tq / KBLK - 1) {
            stage(it + 1, cur ^ 1);
            CP_COMMIT();
            CP_WAIT(1);
        } else {
            CP_WAIT(0);
        }
        __syncthreads();   // tile `cur` staged; all warps past previous compute

        const float* sK  = sm + cur * 2 * FBUF;
        const float* sVt = sK + FBUF;

        // ---- QK^T: S(32x64) = Q * K^T, all 8 s-tiles, C kept in registers ----
        float c[2][8][4];
        #pragma unroll
        for (int mt = 0; mt < 2; ++mt)
            #pragma unroll
            for (int nt = 0; nt < 8; ++nt)
                #pragma unroll
                for (int e = 0; e < 4; ++e) c[mt][nt][e] = 0.f;

        #pragma unroll
        for (int k = 0; k < 8; ++k) {
            #pragma unroll
            for (int nt = 0; nt < 8; ++nt) {
                const int s = nt * 8 + lg;
                float2 v = *(const float2*)(sK + s * PKV + k * 8 + 2 * lt);
                uint32_t bf[2] = { f2u(v.x), f2u(v.y) };
                mma_tf32(c[0][nt], aQ[0][k], bf);
                mma_tf32(c[1][nt], aQ[1][k], bf);
            }
        }

        // ---- exp in registers (scale pre-folded into Q); row sums ----
        #pragma unroll
        for (int mt = 0; mt < 2; ++mt) {
            #pragma unroll
            for (int nt = 0; nt < 8; ++nt) {
                float p0 = ex2f(c[mt][nt][0]);
                float p1 = ex2f(c[mt][nt][1]);
                float p2 = ex2f(c[mt][nt][2]);
                float p3 = ex2f(c[mt][nt][3]);
                rs[mt * 2 + 0] += p0 + p1;
                rs[mt * 2 + 1] += p2 + p3;
                c[mt][nt][0] = p0; c[mt][nt][1] = p1;
                c[mt][nt][2] = p2; c[mt][nt][3] = p3;
            }
        }

        // ---- PV: O += P(32x64) * V(64x64). P C-frag reused as A-frag:
        //      A = {c0, c2, c1, c3}; Vt row pairs (2lt, 2lt+1) match. ----
        #pragma unroll
        for (int k = 0; k < 8; ++k) {
            #pragma unroll
            for (int nt = 0; nt < 8; ++nt) {
                const int d = nt * 8 + lg;
                float2 v = *(const float2*)(sVt + d * PKV + k * 8 + 2 * lt);
                mma_tf32s(o[0][nt], c[0][k][0], c[0][k][2], c[0][k][1], c[0][k][3], v.x, v.y);
                mma_tf32s(o[1][nt], c[1][k][0], c[1][k][2], c[1][k][1], c[1][k][3], v.x, v.y);
            }
        }
        __syncthreads();   // all warps done with buf `cur` before restaging
    }

    // ---- row sums (reduce over the 4 lanes of each row quad) ----
    float inv[4];
    #pragma unroll
    for (int i = 0; i < 4; ++i) {
        float v = rs[i];
        v += __shfl_xor_sync(0xffffffffu, v, 1);
        v += __shfl_xor_sync(0xffffffffu, v, 2);
        inv[i] = 1.f / v;
    }

    // ---- epilogue: O/l + V residual -> out[b, t, h*64 + d] ----
    #pragma unroll
    for (int mt = 0; mt < 2; ++mt) {
        #pragma unroll
        for (int half = 0; half < 2; ++half) {
            const int t  = wq + mt * 16 + half * 8 + lg;
            const float iv = inv[mt * 2 + half];
            const float2* vr = (const float2*)(g_V + ((size_t)bh * Tq + t) * Dq);
            float2* op = (float2*)(out + ((size_t)(b * Tq + t)) * Eq + h * Dq);
            #pragma unroll
            for (int nt = 0; nt < 8; ++nt) {
                const int idx = nt * 4 + lt;
                float2 v = vr[idx];
                op[idx] = make_float2(o[mt][nt][half * 2 + 0] * iv + v.x,
                                      o[mt][nt][half * 2 + 1] * iv + v.y);
            }
        }
    }
}

// ============================================================================
extern "C" void kernel_launch(void* const* d_in, const int* in_sizes, int n_in,
                              void* d_out, int out_size)
{
    const float* x  = (const float*)d_in[0];
    const float* Wq = (const float*)d_in[1];
    const float* Wk = (const float*)d_in[2];
    const float* Wv = (const float*)d_in[3];
    float* out = (float*)d_out;

    const int smem_bytes = SMF_TOTAL * 4;   // 73728 B
    cudaFuncSetAttribute(attn_kernel, cudaFuncAttributeMaxDynamicSharedMemorySize, smem_bytes);

    dim3 pgrid(Tq / 64, BHq);
    proj_kernel<<<pgrid, 64>>>(x, Wq, Wk, Wv);

    dim3 agrid(Tq / QBLK, BHq);
    attn_kernel<<<agrid, 256, smem_bytes>>>(out);
}